// round 9
// baseline (speedup 1.0000x reference)
#include <cuda_runtime.h>

#define Bc 2
#define Tc 2048
#define Cc 512
#define Hc 8
#define HDc 64
#define TOPKc 64
#define BHc (Bc*Hc)
#define Mr (Bc*Tc)
#define QT 8
#define KT 128

// Scratch (device globals; allocations forbidden)
__device__ float g_Qh[BHc*Tc*HDc];
__device__ float g_Kh[BHc*Tc*HDc];
__device__ float g_Vh[BHc*Tc*HDc];
__device__ float g_Y [Bc*Tc*Cc];

// ---------------------------------------------------------------------------
// helpers
// ---------------------------------------------------------------------------
__device__ __forceinline__ unsigned f2u(float f) {
    unsigned b = __float_as_uint(f);
    return b ^ ((unsigned)((int)b >> 31) | 0x80000000u);
}
__device__ __forceinline__ float u2f(unsigned u) {
    unsigned b = (u & 0x80000000u) ? (u ^ 0x80000000u) : ~u;
    return __uint_as_float(b);
}

// ---------------------------------------------------------------------------
// Fused QKV GEMM: BM=128, BN=64, BK=8, 256 thr, 8x4 micro, double buffer,
// 3 blocks/SM (wave-tail fix: 768 blocks / 444 slots = 1.73 waves of
// half-size tiles vs 2.0 waves of full tiles).
// z==2 (V): fused per-head row-norm in epilogue (BN=64 = exactly one head).
// ---------------------------------------------------------------------------
__global__ void __launch_bounds__(256, 3)
qkv_kernel(const float* __restrict__ A,
           const float* __restrict__ Wq, const float* __restrict__ bq,
           const float* __restrict__ Wk, const float* __restrict__ bk,
           const float* __restrict__ Wv, const float* __restrict__ bv,
           float* __restrict__ Qh, float* __restrict__ Kh, float* __restrict__ Vh)
{
    int z = blockIdx.z;
    const float* W    = (z == 0) ? Wq : (z == 1) ? Wk : Wv;
    const float* bias = (z == 0) ? bq : (z == 1) ? bk : bv;
    float* out        = (z == 0) ? Qh : (z == 1) ? Kh : Vh;

    __shared__ float As[2][8][128];
    __shared__ float Bs[2][8][64];

    int tid = threadIdx.x;
    int bm = blockIdx.y * 128;
    int bn = blockIdx.x * 64;
    int ty = tid >> 4;            // 0..15 -> rows ty*8..ty*8+7
    int tx = tid & 15;            // 0..15 -> cols tx*4..tx*4+3

    int arow = tid >> 1;          // 0..127
    int akq  = (tid & 1) * 4;     // 0 or 4
    int brow = tid >> 5;          // 0..7
    int bcol = (tid & 31) * 2;    // 0..62

    const float* Ag = A + (size_t)(bm + arow) * Cc + akq;
    const float* Wg = W + (size_t)brow * Cc + bn + bcol;

    float acc[8][4];
    #pragma unroll
    for (int i = 0; i < 8; i++)
        #pragma unroll
        for (int j = 0; j < 4; j++) acc[i][j] = 0.f;

    {
        float4 av = *reinterpret_cast<const float4*>(Ag);
        float2 bv2 = *reinterpret_cast<const float2*>(Wg);
        As[0][akq + 0][arow] = av.x;
        As[0][akq + 1][arow] = av.y;
        As[0][akq + 2][arow] = av.z;
        As[0][akq + 3][arow] = av.w;
        *reinterpret_cast<float2*>(&Bs[0][brow][bcol]) = bv2;
    }
    __syncthreads();

    #pragma unroll 1
    for (int kb = 0; kb < 64; kb++) {
        int cur = kb & 1;
        float4 an; float2 bnv;
        if (kb < 63) {
            an  = *reinterpret_cast<const float4*>(Ag + (kb + 1) * 8);
            bnv = *reinterpret_cast<const float2*>(Wg + (size_t)(kb + 1) * 8 * Cc);
        }
        #pragma unroll
        for (int k = 0; k < 8; k++) {
            float4 a0 = *reinterpret_cast<const float4*>(&As[cur][k][ty * 8]);
            float4 a1 = *reinterpret_cast<const float4*>(&As[cur][k][ty * 8 + 4]);
            float4 b0 = *reinterpret_cast<const float4*>(&Bs[cur][k][tx * 4]);
            float a[8] = {a0.x, a0.y, a0.z, a0.w, a1.x, a1.y, a1.z, a1.w};
            float b[4] = {b0.x, b0.y, b0.z, b0.w};
            #pragma unroll
            for (int i = 0; i < 8; i++)
                #pragma unroll
                for (int j = 0; j < 4; j++)
                    acc[i][j] += a[i] * b[j];
        }
        if (kb < 63) {
            int nxt = cur ^ 1;
            As[nxt][akq + 0][arow] = an.x;
            As[nxt][akq + 1][arow] = an.y;
            As[nxt][akq + 2][arow] = an.z;
            As[nxt][akq + 3][arow] = an.w;
            *reinterpret_cast<float2*>(&Bs[nxt][brow][bcol]) = bnv;
            __syncthreads();
        }
    }

    float4 bia = *reinterpret_cast<const float4*>(bias + bn + tx * 4);
    int h = bn >> 6;                 // BN=64: exactly one head per block
    int dd = (bn & 63) + tx * 4;     // = tx*4 since bn is a multiple of 64
    #pragma unroll
    for (int i = 0; i < 8; i++) {
        int mrow = bm + ty * 8 + i;
        int b = mrow >> 11;
        int t = mrow & (Tc - 1);
        float4 o = make_float4(acc[i][0] + bia.x, acc[i][1] + bia.y,
                               acc[i][2] + bia.z, acc[i][3] + bia.w);
        if (z == 2) {
            // row-norm over this head: 16 tx lanes of same ty = one half-warp
            float ss = o.x*o.x + o.y*o.y + o.z*o.z + o.w*o.w;
            #pragma unroll
            for (int off = 8; off; off >>= 1)
                ss += __shfl_xor_sync(0xffffffffu, ss, off);
            float sc = 1.0f / fmaxf(sqrtf(ss), 1e-12f);
            o.x *= sc; o.y *= sc; o.z *= sc; o.w *= sc;
        }
        *reinterpret_cast<float4*>(out + ((size_t)((b * Hc + h) * Tc + t) << 6) + dd) = o;
    }
}

// ---------------------------------------------------------------------------
// Output projection GEMM (row-major out), scalar FFMA. (128 blocks < 1 wave.)
// ---------------------------------------------------------------------------
__global__ void __launch_bounds__(256, 2)
sgemm_kernel(const float* __restrict__ A, const float* __restrict__ W,
             const float* __restrict__ bias, float* __restrict__ out)
{
    __shared__ float As[2][8][128];
    __shared__ float Bs[2][8][128];

    int tid = threadIdx.x;
    int bm = blockIdx.y * 128;
    int bn = blockIdx.x * 128;
    int ty = tid >> 4;
    int tx = tid & 15;

    int arow = tid >> 1;
    int akq  = (tid & 1) * 4;
    int brow = tid >> 5;
    int bcol = (tid & 31) * 4;

    const float* Ag = A + (size_t)(bm + arow) * Cc + akq;
    const float* Wg = W + (size_t)brow * Cc + bn + bcol;

    float acc[8][8];
    #pragma unroll
    for (int i = 0; i < 8; i++)
        #pragma unroll
        for (int j = 0; j < 8; j++) acc[i][j] = 0.f;

    {
        float4 av = *reinterpret_cast<const float4*>(Ag);
        float4 bv4 = *reinterpret_cast<const float4*>(Wg);
        As[0][akq + 0][arow] = av.x;
        As[0][akq + 1][arow] = av.y;
        As[0][akq + 2][arow] = av.z;
        As[0][akq + 3][arow] = av.w;
        *reinterpret_cast<float4*>(&Bs[0][brow][bcol]) = bv4;
    }
    __syncthreads();

    #pragma unroll 1
    for (int kb = 0; kb < 64; kb++) {
        int cur = kb & 1;
        float4 an, bnv;
        if (kb < 63) {
            an  = *reinterpret_cast<const float4*>(Ag + (kb + 1) * 8);
            bnv = *reinterpret_cast<const float4*>(Wg + (size_t)(kb + 1) * 8 * Cc);
        }
        #pragma unroll
        for (int k = 0; k < 8; k++) {
            float4 a0 = *reinterpret_cast<const float4*>(&As[cur][k][ty * 4]);
            float4 a1 = *reinterpret_cast<const float4*>(&As[cur][k][64 + ty * 4]);
            float4 b0 = *reinterpret_cast<const float4*>(&Bs[cur][k][tx * 4]);
            float4 b1 = *reinterpret_cast<const float4*>(&Bs[cur][k][64 + tx * 4]);
            float a[8] = {a0.x, a0.y, a0.z, a0.w, a1.x, a1.y, a1.z, a1.w};
            float b[8] = {b0.x, b0.y, b0.z, b0.w, b1.x, b1.y, b1.z, b1.w};
            #pragma unroll
            for (int i = 0; i < 8; i++)
                #pragma unroll
                for (int j = 0; j < 8; j++)
                    acc[i][j] += a[i] * b[j];
        }
        if (kb < 63) {
            int nxt = cur ^ 1;
            As[nxt][akq + 0][arow] = an.x;
            As[nxt][akq + 1][arow] = an.y;
            As[nxt][akq + 2][arow] = an.z;
            As[nxt][akq + 3][arow] = an.w;
            *reinterpret_cast<float4*>(&Bs[nxt][brow][bcol]) = bnv;
            __syncthreads();
        }
    }

    float4 bia0 = *reinterpret_cast<const float4*>(bias + bn + tx * 4);
    float4 bia1 = *reinterpret_cast<const float4*>(bias + bn + 64 + tx * 4);
    #pragma unroll
    for (int i = 0; i < 8; i++) {
        int r = (i < 4) ? (ty * 4 + i) : (64 + ty * 4 + (i - 4));
        int mrow = bm + r;
        float4 o0 = make_float4(acc[i][0] + bia0.x, acc[i][1] + bia0.y,
                                acc[i][2] + bia0.z, acc[i][3] + bia0.w);
        float4 o1 = make_float4(acc[i][4] + bia1.x, acc[i][5] + bia1.y,
                                acc[i][6] + bia1.z, acc[i][7] + bia1.w);
        *reinterpret_cast<float4*>(out + (size_t)mrow * Cc + bn + tx * 4) = o0;
        *reinterpret_cast<float4*>(out + (size_t)mrow * Cc + bn + 64 + tx * 4) = o1;
    }
}

// ---------------------------------------------------------------------------
// Attention: identical to round 8 except PV phase uses float4 V loads
// (lane = d-chunk x key-parity, cross-parity shfl reduce).
// ---------------------------------------------------------------------------
struct AttnSmem {
    float qs[QT][HDc];                 // 2 KB
    float kt[KT][68];                  // 34.8 KB
    unsigned su[QT][Tc];               // 64 KB scores / probs
    union RowSel {
        int hist[256];
        unsigned short sidx[512];
    } sel[QT];                         // 8 KB
};

__global__ void __launch_bounds__(256, 2)
attn_kernel(const float* __restrict__ Q, const float* __restrict__ K,
            const float* __restrict__ V, float* __restrict__ Y)
{
    extern __shared__ unsigned char raw[];
    AttnSmem* S = reinterpret_cast<AttnSmem*>(raw);

    int tid  = threadIdx.x;
    int warp = tid >> 5;
    int lane = tid & 31;

    int bh = blockIdx.y;
    int qbase = ((int)gridDim.x - 1 - (int)blockIdx.x) * QT;  // long rows first
    int n_max = qbase + QT;

    const float* Kb = K + (size_t)bh * Tc * HDc;
    const float* Vb = V + (size_t)bh * Tc * HDc;

    if (tid < 128) {
        int r = tid >> 4, i = tid & 15;
        reinterpret_cast<float4*>(S->qs[r])[i] =
            reinterpret_cast<const float4*>(Q + ((size_t)bh * Tc + qbase + r) * HDc)[i];
    }

    // score-phase mapping: 4 rows x quarter keys per warp
    int quarter = warp >> 1;            // 0..3 -> key quarter
    int rgrp = (warp & 1) * 4;          // row group base (4 rows)
    int kqoff = quarter * 32 + lane;    // key offset within tile
    const float4* q40 = reinterpret_cast<const float4*>(S->qs[rgrp + 0]);
    const float4* q41 = reinterpret_cast<const float4*>(S->qs[rgrp + 1]);
    const float4* q42 = reinterpret_cast<const float4*>(S->qs[rgrp + 2]);
    const float4* q43 = reinterpret_cast<const float4*>(S->qs[rgrp + 3]);

    int ldrow = tid >> 4;               // 0..15
    int lddq  = (tid & 15) * 4;

    int ntiles = (n_max + KT - 1) / KT;

    // prologue: tile 0 -> registers
    float4 rv[8];
    #pragma unroll
    for (int i = 0; i < 8; i++)
        rv[i] = *reinterpret_cast<const float4*>(Kb + (size_t)(ldrow + 16 * i) * HDc + lddq);

    #pragma unroll 1
    for (int t = 0; t < ntiles; t++) {
        __syncthreads();
        #pragma unroll
        for (int i = 0; i < 8; i++)
            *reinterpret_cast<float4*>(&S->kt[ldrow + 16 * i][lddq]) = rv[i];
        __syncthreads();

        if (t + 1 < ntiles) {
            int t0n = (t + 1) * KT;
            #pragma unroll
            for (int i = 0; i < 8; i++)
                rv[i] = *reinterpret_cast<const float4*>(
                            Kb + (size_t)(t0n + ldrow + 16 * i) * HDc + lddq);
        }

        float a0 = 0.f, a1 = 0.f, a2 = 0.f, a3 = 0.f;
        #pragma unroll
        for (int i = 0; i < 16; i++) {
            float4 kv = *reinterpret_cast<const float4*>(&S->kt[kqoff][i * 4]);
            float4 qa = q40[i], qb = q41[i], qc = q42[i], qd = q43[i];
            a0 += qa.x * kv.x + qa.y * kv.y + qa.z * kv.z + qa.w * kv.w;
            a1 += qb.x * kv.x + qb.y * kv.y + qb.z * kv.z + qb.w * kv.w;
            a2 += qc.x * kv.x + qc.y * kv.y + qc.z * kv.z + qc.w * kv.w;
            a3 += qd.x * kv.x + qd.y * kv.y + qd.z * kv.z + qd.w * kv.w;
        }
        int k = t * KT + kqoff;
        if (k <= qbase + rgrp + 0) S->su[rgrp + 0][k] = f2u(a0 * 0.125f);
        if (k <= qbase + rgrp + 1) S->su[rgrp + 1][k] = f2u(a1 * 0.125f);
        if (k <= qbase + rgrp + 2) S->su[rgrp + 2][k] = f2u(a2 * 0.125f);
        if (k <= qbase + rgrp + 3) S->su[rgrp + 3][k] = f2u(a3 * 0.125f);
    }
    __syncthreads();   // all scores visible; switch to warp<->row mapping

    int row = warp;
    int qi = qbase + row;
    int n = qi + 1;
    unsigned* su = S->su[row];

    // ---- exact rank-64 threshold: 4-pass byte radix (atomics form)
    unsigned thrU = 0u;
    if (n > TOPKc) {
        unsigned pref = 0u; int need = TOPKc;
        #pragma unroll 1
        for (int by = 3; by >= 0; --by) {
            int sh = by * 8;
            #pragma unroll
            for (int b = lane; b < 256; b += 32) S->sel[row].hist[b] = 0;
            __syncwarp();
            if (by == 3) {
                for (int k = lane; k < n; k += 32) {
                    unsigned u = su[k];
                    atomicAdd(&S->sel[row].hist[u >> 24], 1);
                }
            } else {
                unsigned hp = pref >> (sh + 8);
                for (int k = lane; k < n; k += 32) {
                    unsigned u = su[k];
                    if ((u >> (sh + 8)) == hp)
                        atomicAdd(&S->sel[row].hist[(u >> sh) & 255u], 1);
                }
            }
            __syncwarp();
            int s = 0;
            #pragma unroll
            for (int j = 0; j < 8; j++) s += S->sel[row].hist[255 - lane * 8 - j];
            int cum = s;
            #pragma unroll
            for (int off = 1; off < 32; off <<= 1) {
                int v = __shfl_up_sync(0xffffffffu, cum, off);
                if (lane >= off) cum += v;
            }
            unsigned bal = __ballot_sync(0xffffffffu, cum >= need);
            int selL = __ffs(bal) - 1;
            int above = __shfl_sync(0xffffffffu, cum - s, selL);
            int sneed = need - above;
            int res = 0;
            if (lane == selL) {
                int c = 0;
                #pragma unroll 1
                for (int j = 0; j < 8; j++) {
                    int b = 255 - selL * 8 - j;
                    int h = S->sel[row].hist[b];
                    if (c + h >= sneed) { res = (b << 16) | (sneed - c); break; }
                    c += h;
                }
            }
            res = __shfl_sync(0xffffffffu, res, selL);
            pref |= (unsigned)(res >> 16) << sh;
            need = res & 0xffff;
        }
        thrU = pref;
    }
    __syncwarp();

    // ---- ballot compaction (ordered) + row max
    unsigned short* sidx = S->sel[row].sidx;
    int m = 0; unsigned umax = 0u;
    #pragma unroll 1
    for (int k0 = 0; k0 < n; k0 += 32) {
        int k = k0 + lane;
        bool a = k < n;
        unsigned u = a ? su[k] : 0u;
        umax = max(umax, u);
        bool keep = a && (u >= thrU);
        unsigned bal = __ballot_sync(0xffffffffu, keep);
        if (keep) {
            int pos = m + __popc(bal & ((1u << lane) - 1u));
            if (pos < 512) sidx[pos] = (unsigned short)k;
        }
        m += __popc(bal);
    }
    if (m > 512) m = 512;
    #pragma unroll
    for (int off = 16; off; off >>= 1)
        umax = max(umax, __shfl_xor_sync(0xffffffffu, umax, off));

    // ---- softmax over survivors (probs overwrite su in place)
    float maxf = u2f(umax);
    float lsum = 0.f;
    for (int j = lane; j < m; j += 32) {
        int k = sidx[j];
        float p = __expf(u2f(su[k]) - maxf);
        su[k] = __float_as_uint(p);
        lsum += p;
    }
    __syncwarp();
    #pragma unroll
    for (int off = 16; off; off >>= 1) lsum += __shfl_xor_sync(0xffffffffu, lsum, off);
    float rinv = 1.0f / lsum;

    // ---- sparse PV: lane = d-chunk (lane&15)*4 x key-parity (lane>>4)
    const float4* V4 = reinterpret_cast<const float4*>(Vb);   // 16 float4 per key
    int dq = lane & 15;
    int kpar = lane >> 4;
    float4 y4 = make_float4(0.f, 0.f, 0.f, 0.f);
    int j = kpar;
    for (; j + 4 <= m; j += 4) {
        int k0 = sidx[j];
        int k1 = sidx[j + 2];
        float p0 = __uint_as_float(su[k0]);
        float p1 = __uint_as_float(su[k1]);
        float4 v0 = V4[(size_t)k0 * 16 + dq];
        float4 v1 = V4[(size_t)k1 * 16 + dq];
        y4.x += p0 * v0.x + p1 * v1.x;
        y4.y += p0 * v0.y + p1 * v1.y;
        y4.z += p0 * v0.z + p1 * v1.z;
        y4.w += p0 * v0.w + p1 * v1.w;
    }
    for (; j < m; j += 2) {
        int k = sidx[j];
        float p = __uint_as_float(su[k]);
        float4 v = V4[(size_t)k * 16 + dq];
        y4.x += p * v.x; y4.y += p * v.y; y4.z += p * v.z; y4.w += p * v.w;
    }
    // combine the two key-parity partials (lane ^ 16 holds the other parity)
    y4.x += __shfl_xor_sync(0xffffffffu, y4.x, 16);
    y4.y += __shfl_xor_sync(0xffffffffu, y4.y, 16);
    y4.z += __shfl_xor_sync(0xffffffffu, y4.z, 16);
    y4.w += __shfl_xor_sync(0xffffffffu, y4.w, 16);
    if (lane < 16) {
        int b = bh >> 3, h = bh & 7;
        *reinterpret_cast<float4*>(Y + (size_t)(b * Tc + qi) * Cc + h * HDc + dq * 4) =
            make_float4(y4.x * rinv, y4.y * rinv, y4.z * rinv, y4.w * rinv);
    }
}

// ---------------------------------------------------------------------------
extern "C" void kernel_launch(void* const* d_in, const int* in_sizes, int n_in,
                              void* d_out, int out_size)
{
    const float* q  = (const float*)d_in[0];
    const float* Wq = (const float*)d_in[2];
    const float* bq = (const float*)d_in[3];
    const float* Wk = (const float*)d_in[4];
    const float* bk = (const float*)d_in[5];
    const float* Wv = (const float*)d_in[6];
    const float* bv = (const float*)d_in[7];
    const float* Wp = (const float*)d_in[8];
    const float* bp = (const float*)d_in[9];

    float *Qh, *Kh, *Vh, *Yb;
    cudaGetSymbolAddress((void**)&Qh, g_Qh);
    cudaGetSymbolAddress((void**)&Kh, g_Kh);
    cudaGetSymbolAddress((void**)&Vh, g_Vh);
    cudaGetSymbolAddress((void**)&Yb, g_Y);

    cudaFuncSetAttribute(attn_kernel, cudaFuncAttributeMaxDynamicSharedMemorySize,
                         (int)sizeof(AttnSmem));

    qkv_kernel<<<dim3(Cc / 64, Mr / 128, 3), 256>>>(q, Wq, bq, Wk, bk, Wv, bv, Qh, Kh, Vh);
    attn_kernel<<<dim3(Tc / QT, BHc), 256, sizeof(AttnSmem)>>>(Qh, Kh, Vh, Yb);
    sgemm_kernel<<<dim3(Cc / 128, Mr / 128), 256>>>(Yb, Wp, bp, (float*)d_out);
}